// round 14
// baseline (speedup 1.0000x reference)
#include <cuda_runtime.h>
#include <cstdint>

#define BB 4
#define NN 4096
#define DD 1024
#define EE 64
#define CAP 128
#define NT (BB*NN)                       // 16384 tokens
#define BNEC ((size_t)NT*EE*CAP)         // 134217728 elements per big tensor
#define THRESH 0.2f
#define NB 256                           // gating blocks (64 tokens each)
#define TOT4 67108864UL                  // total zero-fill in float4 = 2*BNEC/4
#define NZB  32768                       // writer blocks: 32768 * 2048 = TOT4

#define CP_ASYNC16(dst_u32, src_ptr) \
    asm volatile("cp.async.cg.shared.global [%0], [%1], 16;" :: "r"(dst_u32), "l"(src_ptr) : "memory")
#define CP_COMMIT() asm volatile("cp.async.commit_group;" ::: "memory")
#define CP_WAIT(n)  asm volatile("cp.async.wait_group %0;" :: "n"(n) : "memory")

// ---------------- scratch (no allocations allowed) ----------------
__device__ int   g_idx1[NT], g_idx2[NT];
__device__ float g_g1[NT],  g_g2[NT];
__device__ int   g_pos1[NT], g_pos2[NT];
__device__ float g_dens_p[NB][EE];       // per-gating-block partials (no atomics, no init)
__device__ int   g_cnt_p[NB][EE];        // per-chunk top-1 histogram (scan input)
__device__ int   g_cnt2_p[NB][EE];       // per-chunk thresholded top-2 histogram
__device__ float g_lse_p[NB];

// ---------------- KZ: pure zero writer (own kernel => own low reg count, high occ) ----------------
__global__ __launch_bounds__(256) void zero_kernel(float* __restrict__ out) {
    const size_t base = (size_t)blockIdx.x * 2048 + threadIdx.x;
    float4* __restrict__ o4 = (float4*)out;
    const float4 z4 = make_float4(0.f, 0.f, 0.f, 0.f);
    #pragma unroll
    for (int i = 0; i < 8; i++)
        __stcs(&o4[base + (size_t)i * 256], z4);
}

// ---------------- KG: GEMM + softmax + top2 + aux partials + chunk histograms ----------------
// R13-proven pipelined GEMM path, now its own kernel (runs concurrently with zero_kernel).
__global__ __launch_bounds__(256) void gemm_kernel(const float* __restrict__ x,
                                                   const float* __restrict__ w) {
    const int tid = threadIdx.x;
    const int bid = blockIdx.x;

    __shared__ union {
        struct {
            float xs[4][64][16];   // [stage][token][k-within-chunk]
            float ws[4][16][64];   // [stage][k][expert]
        } p;
        struct {
            float logits[64][65];  // padded; overwritten in-place by probs
            float sm_invS[64];
            int   scnt[64];
            int   scnt2[64];
        } g;
    } sm;

    const int t0 = bid * 64;
    const int eg = tid & 15, tg = tid >> 4;

    float acc[4][4];
    #pragma unroll
    for (int i = 0; i < 4; i++)
        #pragma unroll
        for (int j = 0; j < 4; j++) acc[i][j] = 0.f;

    const int xtok = tid >> 2, xkq = tid & 3;   // x loader: 64 tok x 4 quads
    const int wkk  = tid >> 4, weq = tid & 15;  // w loader: 16 k x 16 quads

    const float4* xg = (const float4*)(x) + (size_t)(t0 + xtok) * (DD/4) + xkq;
    const float4* wg = (const float4*)(w) + (size_t)wkk * (EE/4) + weq;

    uint32_t xdst[4], wdst[4];
    #pragma unroll
    for (int s = 0; s < 4; s++) {
        xdst[s] = (uint32_t)__cvta_generic_to_shared(&sm.p.xs[s][xtok][xkq*4]);
        wdst[s] = (uint32_t)__cvta_generic_to_shared(&sm.p.ws[s][wkk][weq*4]);
    }

    #pragma unroll
    for (int p = 0; p < 3; p++) {
        CP_ASYNC16(xdst[p], xg + (size_t)p * 4);
        CP_ASYNC16(wdst[p], wg + (size_t)p * 16 * (EE/4));
        CP_COMMIT();
    }

    for (int kc = 0; kc < DD/16; kc++) {
        CP_WAIT(2);
        __syncthreads();
        if (kc + 3 < DD/16) {
            const int s = (kc + 3) & 3;
            CP_ASYNC16(xdst[s], xg + (size_t)(kc + 3) * 4);
            CP_ASYNC16(wdst[s], wg + (size_t)(kc + 3) * 16 * (EE/4));
        }
        CP_COMMIT();

        const int s = kc & 3;
        #pragma unroll
        for (int kq = 0; kq < 4; kq++) {
            float4 av[4];
            #pragma unroll
            for (int i = 0; i < 4; i++)
                av[i] = *(const float4*)&sm.p.xs[s][tg*4 + i][kq*4];
            #pragma unroll
            for (int kk = 0; kk < 4; kk++) {
                const float4 bv = *(const float4*)&sm.p.ws[s][kq*4 + kk][eg*4];
                #pragma unroll
                for (int i = 0; i < 4; i++) {
                    const float ai = ((const float*)&av[i])[kk];
                    acc[i][0] += ai * bv.x;
                    acc[i][1] += ai * bv.y;
                    acc[i][2] += ai * bv.z;
                    acc[i][3] += ai * bv.w;
                }
            }
        }
    }

    CP_WAIT(0);
    __syncthreads();            // pipeline dead; union may flip to gating

    #pragma unroll
    for (int i = 0; i < 4; i++)
        #pragma unroll
        for (int j = 0; j < 4; j++)
            sm.g.logits[tg*4 + i][eg*4 + j] = acc[i][j];

    if (tid < 64) { sm.g.scnt[tid] = 0; sm.g.scnt2[tid] = 0; }
    __syncthreads();

    float my_lse = 0.f;
    if (tid < 64) {
        const int t = tid;
        float best1 = -3.4e38f, best2 = -3.4e38f;
        int i1 = 0, i2 = 0;
        #pragma unroll 4
        for (int e = 0; e < EE; e++) {
            float l = sm.g.logits[t][e];
            if (l > best1) { best2 = best1; i2 = i1; best1 = l; i1 = e; }
            else if (l > best2) { best2 = l; i2 = e; }
        }
        float S = 0.f;
        #pragma unroll 4
        for (int e = 0; e < EE; e++) {
            float p = __expf(sm.g.logits[t][e] - best1);
            sm.g.logits[t][e] = p;               // in-place: row t owned by thread t
            S += p;
        }
        float invS = 1.0f / S;
        sm.g.sm_invS[t] = invS;
        float g1 = invS;
        float g2 = __expf(best2 - best1) * invS;
        float denom = g1 + g2 + 1e-9f;
        float g1n = g1 / denom, g2n = g2 / denom;
        g_idx1[t0 + t] = i1;
        g_idx2[t0 + t] = i2;
        g_g1[t0 + t] = g1n;
        g_g2[t0 + t] = g2n;
        atomicAdd(&sm.g.scnt[i1], 1);
        if (g2n > THRESH) atomicAdd(&sm.g.scnt2[i2], 1);
        my_lse = best1 + __logf(S);
    }
    __syncthreads();

    if (tid < 64) {
        float s = 0.f;
        #pragma unroll 4
        for (int t = 0; t < 64; t++) s += sm.g.logits[t][tid] * sm.g.sm_invS[t];
        g_dens_p[bid][tid] = s;
        g_cnt_p[bid][tid]  = sm.g.scnt[tid];
        g_cnt2_p[bid][tid] = sm.g.scnt2[tid];
        #pragma unroll
        for (int o = 16; o > 0; o >>= 1)
            my_lse += __shfl_down_sync(0xffffffffu, my_lse, o);
        if ((tid & 31) == 0) {
            if (tid == 0) sm.g.sm_invS[0] = my_lse;
            else          sm.g.sm_invS[1] = my_lse;
        }
    }
    __syncthreads();
    if (tid == 0) g_lse_p[bid] = sm.g.sm_invS[0] + sm.g.sm_invS[1];
}

// ---------------- KS: chunk-parallel capacity scan (4 blocks, one per batch) ----------------
__global__ __launch_bounds__(1024) void scan_kernel() {
    __shared__ int s_c1[64][64];
    __shared__ int s_c2[64][64];
    __shared__ int hist1[16][64];
    __shared__ int hist2[16][64];

    const int b    = blockIdx.x;
    const int tid  = threadIdx.x;
    const int wid  = tid >> 5;
    const int lane = tid & 31;
    const unsigned lt = (1u << lane) - 1u;

    ((int4*)s_c1)[tid] = ((const int4*)g_cnt_p)[b*1024 + tid];
    ((int4*)s_c2)[tid] = ((const int4*)g_cnt2_p)[b*1024 + tid];
    __syncthreads();

    if (tid < 64) {
        int run = 0;
        #pragma unroll 8
        for (int c = 0; c < 64; c++) { int v = s_c1[c][tid]; s_c1[c][tid] = run; run += v; }
        int run2 = min(run, CAP);
        #pragma unroll 8
        for (int c = 0; c < 64; c++) { int v = s_c2[c][tid]; s_c2[c][tid] = run2; run2 += v; }
    }
    __syncthreads();

    for (int pass = 0; pass < 4; pass++) {
        const int li = pass * 1024 + tid;
        const int t  = b * NN + li;
        const int ch = li >> 6;
        const int hc = tid >> 6;
        const bool upper = (wid & 1);

        ((int*)hist1)[tid] = 0;
        ((int*)hist2)[tid] = 0;
        __syncthreads();

        const int e1   = g_idx1[t];
        const bool v2  = g_g2[t] > THRESH;
        const int e2   = v2 ? g_idx2[t] : -1;

        unsigned m1 = __match_any_sync(0xffffffffu, e1);
        int r1 = __popc(m1 & lt);
        unsigned m2 = __match_any_sync(0xffffffffu, e2);
        int r2 = __popc(m2 & lt);

        if (!upper) {
            if (r1 == 0) hist1[hc][e1] = __popc(m1);
            if (v2 && r2 == 0) hist2[hc][e2] = __popc(m2);
        }
        __syncthreads();

        if (upper) {
            r1 += hist1[hc][e1];
            if (v2) r2 += hist2[hc][e2];
        }

        int p1 = s_c1[ch][e1] + r1;
        g_pos1[t] = (p1 < CAP) ? p1 : -1;
        if (v2) {
            int p2 = s_c2[ch][e2] + r2;
            g_pos2[t] = (p2 < CAP) ? p2 : -1;
        } else {
            g_pos2[t] = -1;
        }
        __syncthreads();
    }
}

// ---------------- KF: scatter nonzeros + finalize scalars (after zeros AND scan) ----------------
__global__ __launch_bounds__(256) void scatter_finalize_kernel(float* __restrict__ out) {
    const int t = blockIdx.x * 256 + threadIdx.x;

    if (t < NT) {
        const int p1 = g_pos1[t], p2 = g_pos2[t];
        const size_t row = (size_t)t * (EE*CAP);

        if (p1 >= 0) {
            const size_t o = row + (size_t)g_idx1[t] * CAP + p1;
            out[o]        = 1.f;       // dispatch
            out[BNEC + o] = g_g1[t];   // combine
        }
        if (p2 >= 0) {
            const size_t o = row + (size_t)g_idx2[t] * CAP + p2;
            out[o]        = 1.f;
            out[BNEC + o] = g_g2[t];
        }
    }

    if (blockIdx.x == 0) {
        __shared__ float red[256];
        const int tid = threadIdx.x;
        const int b = tid >> 6, e = tid & 63;

        float dens = 0.f; int cnt = 0;
        #pragma unroll 8
        for (int c = 0; c < 64; c++) {
            dens += g_dens_p[b*64 + c][e];
            cnt  += g_cnt_p[b*64 + c][e];
        }
        red[tid] = dens * (float)cnt;
        __syncthreads();
        for (int s = 128; s > 0; s >>= 1) {
            if (tid < s) red[tid] += red[tid + s];
            __syncthreads();
        }
        float loss = red[0] * ((float)EE / ((float)BB * (float)NN * (float)NN));
        __syncthreads();

        red[tid] = g_lse_p[tid];
        __syncthreads();
        for (int s = 128; s > 0; s >>= 1) {
            if (tid < s) red[tid] += red[tid + s];
            __syncthreads();
        }
        if (tid == 0) {
            out[2*BNEC]     = loss;
            out[2*BNEC + 1] = red[0] * (1.0f / (float)BB);
        }
    }
}

// ---------------- launch: fork zero stream || gemm->scan, join, scatter ----------------
extern "C" void kernel_launch(void* const* d_in, const int* in_sizes, int n_in,
                              void* d_out, int out_size) {
    const float* x = (const float*)d_in[0];   // [4,4096,1024] f32
    const float* w = (const float*)d_in[1];   // [1024,64] f32
    float* out = (float*)d_out;               // dispatch | combine | loss | z_loss

    // Created once, on the first (non-captured) correctness call; reused thereafter so
    // every call issues the identical launch sequence (deterministic, capture-safe).
    static cudaStream_t s_zero = nullptr;
    static cudaEvent_t  ev_fork = nullptr, ev_join = nullptr;
    if (s_zero == nullptr) {
        cudaStreamCreateWithFlags(&s_zero, cudaStreamNonBlocking);
        cudaEventCreateWithFlags(&ev_fork, cudaEventDisableTiming);
        cudaEventCreateWithFlags(&ev_join, cudaEventDisableTiming);
    }

    // fork: side stream runs the pure zero writer (bulk of the time)
    cudaEventRecord(ev_fork, 0);
    cudaStreamWaitEvent(s_zero, ev_fork, 0);
    zero_kernel<<<NZB, 256, 0, s_zero>>>(out);
    cudaEventRecord(ev_join, s_zero);

    // main stream: gemm -> scan (runs concurrently with the zero stream)
    gemm_kernel<<<NB, 256>>>(x, w);
    scan_kernel<<<BB, 1024>>>();

    // join: scatter needs both the zeros and the scan results
    cudaStreamWaitEvent(0, ev_join, 0);
    scatter_finalize_kernel<<<NT/256, 256>>>(out);
}

// round 15
// speedup vs baseline: 1.3919x; 1.3919x over previous
#include <cuda_runtime.h>
#include <cstdint>

#define BB 4
#define NN 4096
#define DD 1024
#define EE 64
#define CAP 128
#define NT (BB*NN)                       // 16384 tokens
#define BNEC ((size_t)NT*EE*CAP)         // 134217728 elements per big tensor
#define THRESH 0.2f
#define NB 256                           // gating blocks (64 tokens each)

// zero-fill partition (in float4 units): total = 2*BNEC/4 = 67,108,864
#define TOT4   67108864UL
#define K2Z4   6291456UL                 // 96 MiB handled during scan window
#define K1Z4   (TOT4 - K2Z4)             // 60,817,408 float4
#define NZB    29696                     // PDL zero blocks: 29696 * 2048 = K1Z4
#define K2ZB   384                       // zero blocks in K2
#define K2LANES (K2ZB*1024)              // 393216 lanes * 16 = K2Z4
#define K2PER  16

#define CP_ASYNC16(dst_u32, src_ptr) \
    asm volatile("cp.async.cg.shared.global [%0], [%1], 16;" :: "r"(dst_u32), "l"(src_ptr) : "memory")
#define CP_COMMIT() asm volatile("cp.async.commit_group;" ::: "memory")
#define CP_WAIT(n)  asm volatile("cp.async.wait_group %0;" :: "n"(n) : "memory")

// ---------------- scratch (no allocations allowed) ----------------
__device__ int   g_idx1[NT], g_idx2[NT];
__device__ float g_g1[NT],  g_g2[NT];
__device__ int   g_pos1[NT], g_pos2[NT];
__device__ float g_dens_p[NB][EE];       // per-gating-block partials (no atomics, no init)
__device__ int   g_cnt_p[NB][EE];        // per-chunk top-1 histogram (scan input)
__device__ int   g_cnt2_p[NB][EE];       // per-chunk thresholded top-2 histogram
__device__ float g_lse_p[NB];

// ---------------- K1a: GEMM (fires PDL trigger at entry) ----------------
__global__ __launch_bounds__(256) void gemm_kernel(const float* __restrict__ x,
                                                   const float* __restrict__ w) {
#if __CUDA_ARCH__ >= 900
    cudaTriggerProgrammaticLaunchCompletion();   // let the zero writer start now
#endif
    const int tid = threadIdx.x;
    const int bid = blockIdx.x;

    __shared__ union {
        struct {
            float xs[4][64][16];   // [stage][token][k-within-chunk]
            float ws[4][16][64];   // [stage][k][expert]
        } p;
        struct {
            float logits[64][65];  // padded; overwritten in-place by probs
            float sm_invS[64];
            int   scnt[64];
            int   scnt2[64];
        } g;
    } sm;

    const int t0 = bid * 64;
    const int eg = tid & 15, tg = tid >> 4;

    float acc[4][4];
    #pragma unroll
    for (int i = 0; i < 4; i++)
        #pragma unroll
        for (int j = 0; j < 4; j++) acc[i][j] = 0.f;

    const int xtok = tid >> 2, xkq = tid & 3;   // x loader: 64 tok x 4 quads
    const int wkk  = tid >> 4, weq = tid & 15;  // w loader: 16 k x 16 quads

    const float4* xg = (const float4*)(x) + (size_t)(t0 + xtok) * (DD/4) + xkq;
    const float4* wg = (const float4*)(w) + (size_t)wkk * (EE/4) + weq;

    uint32_t xdst[4], wdst[4];
    #pragma unroll
    for (int s = 0; s < 4; s++) {
        xdst[s] = (uint32_t)__cvta_generic_to_shared(&sm.p.xs[s][xtok][xkq*4]);
        wdst[s] = (uint32_t)__cvta_generic_to_shared(&sm.p.ws[s][wkk][weq*4]);
    }

    #pragma unroll
    for (int p = 0; p < 3; p++) {
        CP_ASYNC16(xdst[p], xg + (size_t)p * 4);
        CP_ASYNC16(wdst[p], wg + (size_t)p * 16 * (EE/4));
        CP_COMMIT();
    }

    for (int kc = 0; kc < DD/16; kc++) {
        CP_WAIT(2);
        __syncthreads();
        if (kc + 3 < DD/16) {
            const int s = (kc + 3) & 3;
            CP_ASYNC16(xdst[s], xg + (size_t)(kc + 3) * 4);
            CP_ASYNC16(wdst[s], wg + (size_t)(kc + 3) * 16 * (EE/4));
        }
        CP_COMMIT();

        const int s = kc & 3;
        #pragma unroll
        for (int kq = 0; kq < 4; kq++) {
            float4 av[4];
            #pragma unroll
            for (int i = 0; i < 4; i++)
                av[i] = *(const float4*)&sm.p.xs[s][tg*4 + i][kq*4];
            #pragma unroll
            for (int kk = 0; kk < 4; kk++) {
                const float4 bv = *(const float4*)&sm.p.ws[s][kq*4 + kk][eg*4];
                #pragma unroll
                for (int i = 0; i < 4; i++) {
                    const float ai = ((const float*)&av[i])[kk];
                    acc[i][0] += ai * bv.x;
                    acc[i][1] += ai * bv.y;
                    acc[i][2] += ai * bv.z;
                    acc[i][3] += ai * bv.w;
                }
            }
        }
    }

    CP_WAIT(0);
    __syncthreads();            // pipeline dead; union may flip to gating

    #pragma unroll
    for (int i = 0; i < 4; i++)
        #pragma unroll
        for (int j = 0; j < 4; j++)
            sm.g.logits[tg*4 + i][eg*4 + j] = acc[i][j];

    if (tid < 64) { sm.g.scnt[tid] = 0; sm.g.scnt2[tid] = 0; }
    __syncthreads();

    float my_lse = 0.f;
    if (tid < 64) {
        const int t = tid;
        float best1 = -3.4e38f, best2 = -3.4e38f;
        int i1 = 0, i2 = 0;
        #pragma unroll 4
        for (int e = 0; e < EE; e++) {
            float l = sm.g.logits[t][e];
            if (l > best1) { best2 = best1; i2 = i1; best1 = l; i1 = e; }
            else if (l > best2) { best2 = l; i2 = e; }
        }
        float S = 0.f;
        #pragma unroll 4
        for (int e = 0; e < EE; e++) {
            float p = __expf(sm.g.logits[t][e] - best1);
            sm.g.logits[t][e] = p;               // in-place: row t owned by thread t
            S += p;
        }
        float invS = 1.0f / S;
        sm.g.sm_invS[t] = invS;
        float g1 = invS;
        float g2 = __expf(best2 - best1) * invS;
        float denom = g1 + g2 + 1e-9f;
        float g1n = g1 / denom, g2n = g2 / denom;
        g_idx1[t0 + t] = i1;
        g_idx2[t0 + t] = i2;
        g_g1[t0 + t] = g1n;
        g_g2[t0 + t] = g2n;
        atomicAdd(&sm.g.scnt[i1], 1);
        if (g2n > THRESH) atomicAdd(&sm.g.scnt2[i2], 1);
        my_lse = best1 + __logf(S);
    }
    __syncthreads();

    if (tid < 64) {
        float s = 0.f;
        #pragma unroll 4
        for (int t = 0; t < 64; t++) s += sm.g.logits[t][tid] * sm.g.sm_invS[t];
        g_dens_p[bid][tid] = s;
        g_cnt_p[bid][tid]  = sm.g.scnt[tid];
        g_cnt2_p[bid][tid] = sm.g.scnt2[tid];
        #pragma unroll
        for (int o = 16; o > 0; o >>= 1)
            my_lse += __shfl_down_sync(0xffffffffu, my_lse, o);
        if ((tid & 31) == 0) {
            if (tid == 0) sm.g.sm_invS[0] = my_lse;
            else          sm.g.sm_invS[1] = my_lse;
        }
    }
    __syncthreads();
    if (tid == 0) g_lse_p[bid] = sm.g.sm_invS[0] + sm.g.sm_invS[1];
}

// ---------------- K1b: pure zero writer (PDL secondary: overlaps the GEMM) ----------------
// Own kernel => own low reg count, zero smem => high store-warp occupancy.
__global__ __launch_bounds__(256) void zero_kernel(float* __restrict__ out) {
    const size_t base = (size_t)blockIdx.x * 2048 + threadIdx.x;
    float4* __restrict__ o4 = (float4*)out;
    const float4 z4 = make_float4(0.f, 0.f, 0.f, 0.f);
    #pragma unroll
    for (int i = 0; i < 8; i++)
        __stcs(&o4[base + (size_t)i * 256], z4);
}

// ---------------- K2: chunk-parallel scan (blocks 0..3) + zero-fill (blocks 4..387) ----------------
__global__ __launch_bounds__(1024) void scan_zero_kernel(float* __restrict__ out) {
    // ---- zero-fill blocks: cover the last 96 MiB while the scan runs ----
    if (blockIdx.x >= 4) {
        const unsigned lane = (blockIdx.x - 4) * 1024u + threadIdx.x;
        float4* __restrict__ o4 = (float4*)out + K1Z4;
        const float4 z4 = make_float4(0.f, 0.f, 0.f, 0.f);
        size_t q = lane;
        #pragma unroll
        for (int i = 0; i < K2PER; i++) {
            __stcs(&o4[q], z4);
            q += (size_t)K2LANES;
        }
        return;
    }

    __shared__ int s_c1[64][64];     // chunk-hist, overwritten in-place by exclusive prefix
    __shared__ int s_c2[64][64];
    __shared__ int hist1[16][64];    // per-pass lower-half-warp histograms
    __shared__ int hist2[16][64];

    const int b    = blockIdx.x;
    const int tid  = threadIdx.x;
    const int wid  = tid >> 5;
    const int lane = tid & 31;
    const unsigned lt = (1u << lane) - 1u;

    ((int4*)s_c1)[tid] = ((const int4*)g_cnt_p)[b*1024 + tid];
    ((int4*)s_c2)[tid] = ((const int4*)g_cnt2_p)[b*1024 + tid];
    __syncthreads();

    if (tid < 64) {
        int run = 0;
        #pragma unroll 8
        for (int c = 0; c < 64; c++) { int v = s_c1[c][tid]; s_c1[c][tid] = run; run += v; }
        int run2 = min(run, CAP);
        #pragma unroll 8
        for (int c = 0; c < 64; c++) { int v = s_c2[c][tid]; s_c2[c][tid] = run2; run2 += v; }
    }
    __syncthreads();

    for (int pass = 0; pass < 4; pass++) {
        const int li = pass * 1024 + tid;
        const int t  = b * NN + li;
        const int ch = li >> 6;
        const int hc = tid >> 6;
        const bool upper = (wid & 1);

        ((int*)hist1)[tid] = 0;
        ((int*)hist2)[tid] = 0;
        __syncthreads();

        const int e1   = g_idx1[t];
        const bool v2  = g_g2[t] > THRESH;
        const int e2   = v2 ? g_idx2[t] : -1;

        unsigned m1 = __match_any_sync(0xffffffffu, e1);
        int r1 = __popc(m1 & lt);
        unsigned m2 = __match_any_sync(0xffffffffu, e2);
        int r2 = __popc(m2 & lt);

        if (!upper) {
            if (r1 == 0) hist1[hc][e1] = __popc(m1);
            if (v2 && r2 == 0) hist2[hc][e2] = __popc(m2);
        }
        __syncthreads();

        if (upper) {
            r1 += hist1[hc][e1];
            if (v2) r2 += hist2[hc][e2];
        }

        int p1 = s_c1[ch][e1] + r1;
        g_pos1[t] = (p1 < CAP) ? p1 : -1;
        if (v2) {
            int p2 = s_c2[ch][e2] + r2;
            g_pos2[t] = (p2 < CAP) ? p2 : -1;
        } else {
            g_pos2[t] = -1;
        }
        __syncthreads();
    }
}

// ---------------- K3: scatter nonzeros + finalize scalars (block 0) ----------------
__global__ __launch_bounds__(256) void scatter_finalize_kernel(float* __restrict__ out) {
    const int t = blockIdx.x * 256 + threadIdx.x;

    if (t < NT) {
        const int p1 = g_pos1[t], p2 = g_pos2[t];
        const size_t row = (size_t)t * (EE*CAP);

        if (p1 >= 0) {
            const size_t o = row + (size_t)g_idx1[t] * CAP + p1;
            out[o]        = 1.f;       // dispatch
            out[BNEC + o] = g_g1[t];   // combine
        }
        if (p2 >= 0) {
            const size_t o = row + (size_t)g_idx2[t] * CAP + p2;
            out[o]        = 1.f;
            out[BNEC + o] = g_g2[t];
        }
    }

    if (blockIdx.x == 0) {
        __shared__ float red[256];
        const int tid = threadIdx.x;
        const int b = tid >> 6, e = tid & 63;

        float dens = 0.f; int cnt = 0;
        #pragma unroll 8
        for (int c = 0; c < 64; c++) {
            dens += g_dens_p[b*64 + c][e];
            cnt  += g_cnt_p[b*64 + c][e];
        }
        red[tid] = dens * (float)cnt;
        __syncthreads();
        for (int s = 128; s > 0; s >>= 1) {
            if (tid < s) red[tid] += red[tid + s];
            __syncthreads();
        }
        float loss = red[0] * ((float)EE / ((float)BB * (float)NN * (float)NN));
        __syncthreads();

        red[tid] = g_lse_p[tid];
        __syncthreads();
        for (int s = 128; s > 0; s >>= 1) {
            if (tid < s) red[tid] += red[tid + s];
            __syncthreads();
        }
        if (tid == 0) {
            out[2*BNEC]     = loss;
            out[2*BNEC + 1] = red[0] * (1.0f / (float)BB);
        }
    }
}

// ---------------- launch: gemm, zero(PDL overlap), scan+zeros, scatter ----------------
extern "C" void kernel_launch(void* const* d_in, const int* in_sizes, int n_in,
                              void* d_out, int out_size) {
    const float* x = (const float*)d_in[0];   // [4,4096,1024] f32
    const float* w = (const float*)d_in[1];   // [1024,64] f32
    float* out = (float*)d_out;               // dispatch | combine | loss | z_loss

    // K1a: GEMM (all 256 blocks resident immediately; trigger fires at entry)
    gemm_kernel<<<NB, 256>>>(x, w);

    // K1b: zero writer as PDL secondary — starts as soon as the GEMM CTAs trigger,
    // overlapping it with its OWN (small) register/smem footprint.
    {
        cudaLaunchConfig_t cfg = {};
        cfg.gridDim  = dim3(NZB);
        cfg.blockDim = dim3(256);
        cfg.dynamicSmemBytes = 0;
        cfg.stream = 0;
        cudaLaunchAttribute attr[1];
        attr[0].id = cudaLaunchAttributeProgrammaticStreamSerialization;
        attr[0].val.programmaticStreamSerializationAllowed = 1;
        cfg.attrs = attr;
        cfg.numAttrs = 1;
        cudaLaunchKernelEx(&cfg, zero_kernel, out);
    }

    // K2: scan (needs GEMM results) + last 96 MiB of zeros
    scan_zero_kernel<<<4 + K2ZB, 1024>>>(out);

    // K3: scatter + scalars (needs scan + all zeros; kernel boundary orders it)
    scatter_finalize_kernel<<<NT/256, 256>>>(out);
}